// round 2
// baseline (speedup 1.0000x reference)
#include <cuda_runtime.h>
#include <cstdint>

#define NMAX 50000
#define EMAX 262144
#define HDIM 256

// ---------------- scratch (no allocations allowed) ----------------
__device__ float g_h[NMAX * HDIM];     // per-type h = x @ W[t]
__device__ float g_acc[NMAX * HDIM];   // per-layer accumulator (sum over types)
__device__ float g_h1[NMAX * HDIM];    // layer-1 output
__device__ float g_as[NMAX];
__device__ float g_ad[NMAX];
__device__ float g_e[EMAX];
__device__ int   g_m[NMAX];
__device__ float g_den[NMAX];

// ---------------- helpers ----------------
__device__ __forceinline__ uint32_t f2tf(float f) {
    uint32_t r;
    asm("cvt.rna.tf32.f32 %0, %1;" : "=r"(r) : "f"(f));
    return r;
}

// monotone int encoding of float for atomicMax-based segment max
__device__ __forceinline__ int fkey(float f) {
    int i = __float_as_int(f);
    return i >= 0 ? i : (i ^ 0x7fffffff);
}
__device__ __forceinline__ float fdec(int k) {
    int i = k >= 0 ? k : (k ^ 0x7fffffff);
    return __int_as_float(i);
}

// ---------------- GEMM: Hout[n,256] = X[n,256] @ W[256,256], tf32 MMA ----------------
// BM=128, BN=64, BK=32, 256 threads (8 warps: 4 in M x 2 in N), warp tile 32x32
__global__ __launch_bounds__(256) void gemm_tf32(
    const float* __restrict__ X, const float* __restrict__ W,
    float* __restrict__ Hout, int nrows)
{
    __shared__ uint32_t As[128][36];   // [m][k], pad to 36 -> conflict-free frag reads
    __shared__ uint32_t Bs[32][72];    // [k][n], pad to 72 -> conflict-free frag reads
    int tid  = threadIdx.x;
    int lane = tid & 31, warp = tid >> 5;
    int wm = warp >> 1, wn = warp & 1;
    int g  = lane >> 2, tig = lane & 3;
    int bm = blockIdx.x * 128;
    int bn = blockIdx.y * 64;

    float acc[2][4][4];
#pragma unroll
    for (int a = 0; a < 2; a++)
#pragma unroll
        for (int b = 0; b < 4; b++)
#pragma unroll
            for (int c = 0; c < 4; c++) acc[a][b][c] = 0.f;

    for (int k0 = 0; k0 < 256; k0 += 32) {
        // stage A tile 128x32
#pragma unroll
        for (int p = 0; p < 4; p++) {
            int r  = (tid >> 3) + p * 32;
            int c4 = (tid & 7) * 4;
            int gr = bm + r;
            float4 v = make_float4(0.f, 0.f, 0.f, 0.f);
            if (gr < nrows) v = *(const float4*)(X + (size_t)gr * 256 + k0 + c4);
            As[r][c4 + 0] = f2tf(v.x); As[r][c4 + 1] = f2tf(v.y);
            As[r][c4 + 2] = f2tf(v.z); As[r][c4 + 3] = f2tf(v.w);
        }
        // stage B tile 32x64
#pragma unroll
        for (int p = 0; p < 2; p++) {
            int r  = (tid >> 4) + p * 16;
            int c4 = (tid & 15) * 4;
            float4 v = *(const float4*)(W + (size_t)(k0 + r) * 256 + bn + c4);
            Bs[r][c4 + 0] = f2tf(v.x); Bs[r][c4 + 1] = f2tf(v.y);
            Bs[r][c4 + 2] = f2tf(v.z); Bs[r][c4 + 3] = f2tf(v.w);
        }
        __syncthreads();

#pragma unroll
        for (int kk = 0; kk < 32; kk += 8) {
            uint32_t a[2][4], b[4][2];
#pragma unroll
            for (int mm = 0; mm < 2; mm++) {
                int row = wm * 32 + mm * 16 + g;
                a[mm][0] = As[row][kk + tig];
                a[mm][1] = As[row + 8][kk + tig];
                a[mm][2] = As[row][kk + tig + 4];
                a[mm][3] = As[row + 8][kk + tig + 4];
            }
#pragma unroll
            for (int nn = 0; nn < 4; nn++) {
                int col = wn * 32 + nn * 8 + g;
                b[nn][0] = Bs[kk + tig][col];
                b[nn][1] = Bs[kk + tig + 4][col];
            }
#pragma unroll
            for (int mm = 0; mm < 2; mm++)
#pragma unroll
                for (int nn = 0; nn < 4; nn++)
                    asm volatile(
                        "mma.sync.aligned.m16n8k8.row.col.f32.tf32.tf32.f32 "
                        "{%0,%1,%2,%3}, {%4,%5,%6,%7}, {%8,%9}, {%0,%1,%2,%3};"
                        : "+f"(acc[mm][nn][0]), "+f"(acc[mm][nn][1]),
                          "+f"(acc[mm][nn][2]), "+f"(acc[mm][nn][3])
                        : "r"(a[mm][0]), "r"(a[mm][1]), "r"(a[mm][2]), "r"(a[mm][3]),
                          "r"(b[nn][0]), "r"(b[nn][1]));
        }
        __syncthreads();
    }

#pragma unroll
    for (int mm = 0; mm < 2; mm++)
#pragma unroll
        for (int nn = 0; nn < 4; nn++) {
            int row = bm + wm * 32 + mm * 16 + g;
            int col = bn + wn * 32 + nn * 8 + 2 * tig;
            if (row < nrows)
                *(float2*)(Hout + (size_t)row * 256 + col) =
                    make_float2(acc[mm][nn][0], acc[mm][nn][1]);
            if (row + 8 < nrows)
                *(float2*)(Hout + (size_t)(row + 8) * 256 + col) =
                    make_float2(acc[mm][nn][2], acc[mm][nn][3]);
        }
}

// ---------------- per-row dots: a_src[i]=h_i . a_s ; a_dst[i]=h_i . a_d ----------------
__global__ __launch_bounds__(256) void rowdot(
    const float* __restrict__ h, const float* __restrict__ avs,
    const float* __restrict__ avd, float* __restrict__ outs,
    float* __restrict__ outd, int nrows)
{
    int w    = (blockIdx.x * blockDim.x + threadIdx.x) >> 5;
    int lane = threadIdx.x & 31;
    if (w >= nrows) return;
    const float4* hr = (const float4*)(h + (size_t)w * 256);
    const float4* s4 = (const float4*)avs;
    const float4* d4 = (const float4*)avd;
    float ss = 0.f, sd = 0.f;
#pragma unroll
    for (int j = 0; j < 2; j++) {
        int idx  = lane + j * 32;
        float4 v = hr[idx];
        float4 a = __ldg(&s4[idx]);
        float4 b = __ldg(&d4[idx]);
        ss += v.x * a.x + v.y * a.y + v.z * a.z + v.w * a.w;
        sd += v.x * b.x + v.y * b.y + v.z * b.z + v.w * b.w;
    }
#pragma unroll
    for (int o = 16; o; o >>= 1) {
        ss += __shfl_xor_sync(0xffffffffu, ss, o);
        sd += __shfl_xor_sync(0xffffffffu, sd, o);
    }
    if (lane == 0) { outs[w] = ss; outd[w] = sd; }
}

// ---------------- init kernels ----------------
__global__ void init_md(int* __restrict__ mk, float* __restrict__ den, int n) {
    int i = blockIdx.x * blockDim.x + threadIdx.x;
    if (i < n) { mk[i] = (int)0x80000000; den[i] = 0.f; }
}

__global__ void init_acc(float* __restrict__ acc, const float* __restrict__ b, int n) {
    int i = blockIdx.x * blockDim.x + threadIdx.x;
    if (i < n * 256) {
        int c = i & 255;
        acc[i] = b[c] + b[256 + c] + b[512 + c];
    }
}

// ---------------- edge passes ----------------
__global__ void edge_score(const int* __restrict__ src, const int* __restrict__ dst,
                           const float* __restrict__ as_, const float* __restrict__ ad_,
                           float* __restrict__ e, int* __restrict__ mk, int ne)
{
    int i = blockIdx.x * blockDim.x + threadIdx.x;
    if (i >= ne) return;
    float v = as_[src[i]] + ad_[dst[i]];
    v = v > 0.f ? v : 0.2f * v;   // leaky_relu 0.2
    e[i] = v;
    atomicMax(&mk[dst[i]], fkey(v));
}

__global__ void edge_exp(const int* __restrict__ dst, float* __restrict__ e,
                         const int* __restrict__ mk, float* __restrict__ den, int ne)
{
    int i = blockIdx.x * blockDim.x + threadIdx.x;
    if (i >= ne) return;
    int d   = dst[i];
    float m = fdec(mk[d]);
    float x = __expf(e[i] - m);
    e[i] = x;
    atomicAdd(&den[d], x);
}

// one warp per edge: acc[dst] += alpha * h[src]  (vector L2 reduction)
__global__ __launch_bounds__(256) void edge_scatter(
    const int* __restrict__ src, const int* __restrict__ dst,
    const float* __restrict__ ex, const float* __restrict__ den,
    const float* __restrict__ h, float* __restrict__ acc, int ne)
{
    int w    = (blockIdx.x * blockDim.x + threadIdx.x) >> 5;
    int lane = threadIdx.x & 31;
    if (w >= ne) return;
    int s = src[w], d = dst[w];
    float alpha = ex[w] / den[d];
    const float4* hr = (const float4*)(h + (size_t)s * 256);
    float* ar = acc + (size_t)d * 256;
#pragma unroll
    for (int j = 0; j < 2; j++) {
        int idx  = lane + j * 32;
        float4 v = hr[idx];
        asm volatile("red.global.add.v4.f32 [%0], {%1,%2,%3,%4};"
                     :: "l"(ar + idx * 4),
                        "f"(v.x * alpha), "f"(v.y * alpha),
                        "f"(v.z * alpha), "f"(v.w * alpha)
                     : "memory");
    }
}

// ---------------- pointwise / head ----------------
__global__ void relu_copy(const float* __restrict__ acc, float* __restrict__ y, int total) {
    int i = blockIdx.x * blockDim.x + threadIdx.x;
    if (i < total) y[i] = fmaxf(acc[i], 0.f);
}

__global__ __launch_bounds__(256) void head_kernel(
    const float* __restrict__ acc, const float* __restrict__ Wh,
    const float* __restrict__ bh, float* __restrict__ out, int nrows)
{
    int w    = (blockIdx.x * blockDim.x + threadIdx.x) >> 5;
    int lane = threadIdx.x & 31;
    if (w >= nrows) return;
    const float4* ar = (const float4*)(acc + (size_t)w * 256);
    const float4* wh = (const float4*)Wh;
    float s = 0.f;
#pragma unroll
    for (int j = 0; j < 2; j++) {
        int idx  = lane + j * 32;
        float4 v = ar[idx];
        float4 q = __ldg(&wh[idx]);
        s += fmaxf(v.x, 0.f) * q.x + fmaxf(v.y, 0.f) * q.y +
             fmaxf(v.z, 0.f) * q.z + fmaxf(v.w, 0.f) * q.w;
    }
#pragma unroll
    for (int o = 16; o; o >>= 1) s += __shfl_xor_sync(0xffffffffu, s, o);
    if (lane == 0) out[w] = 1.f / (1.f + __expf(-(s + bh[0])));
}

// ---------------- host orchestration ----------------
static void run_layer(const float* x, const int* ei,
                      const float* W, const float* av_s, const float* av_d,
                      const float* bias,
                      float* hbuf, float* accbuf, float* asb, float* adb,
                      float* ebuf, int* mkey, float* denb, int n, int ne)
{
    init_acc<<<(n * 256 + 255) / 256, 256>>>(accbuf, bias, n);
    for (int t = 0; t < 3; t++) {
        gemm_tf32<<<dim3((n + 127) / 128, 4), 256>>>(x, W + (size_t)t * 256 * 256, hbuf, n);
        rowdot<<<(n + 7) / 8, 256>>>(hbuf, av_s + t * 256, av_d + t * 256, asb, adb, n);
        init_md<<<(n + 255) / 256, 256>>>(mkey, denb, n);
        const int* src = ei + (size_t)t * 2 * ne;
        const int* dst = src + ne;
        edge_score<<<(ne + 255) / 256, 256>>>(src, dst, asb, adb, ebuf, mkey, ne);
        edge_exp<<<(ne + 255) / 256, 256>>>(dst, ebuf, mkey, denb, ne);
        edge_scatter<<<(ne + 7) / 8, 256>>>(src, dst, ebuf, denb, hbuf, accbuf, ne);
    }
}

extern "C" void kernel_launch(void* const* d_in, const int* in_sizes, int n_in,
                              void* d_out, int out_size)
{
    const float* z   = (const float*)d_in[0];
    const int*   ei  = (const int*)d_in[1];
    const float* W1  = (const float*)d_in[2];
    const float* as1 = (const float*)d_in[3];
    const float* ad1 = (const float*)d_in[4];
    const float* b1  = (const float*)d_in[5];
    const float* W2  = (const float*)d_in[6];
    const float* as2 = (const float*)d_in[7];
    const float* ad2 = (const float*)d_in[8];
    const float* b2  = (const float*)d_in[9];
    const float* Wh  = (const float*)d_in[10];
    const float* bh  = (const float*)d_in[11];
    float* out = (float*)d_out;

    int n  = in_sizes[0] / 256;   // 50000
    int ne = in_sizes[1] / 6;     // 250000

    void* p;
    cudaGetSymbolAddress(&p, g_h);   float* hbuf   = (float*)p;
    cudaGetSymbolAddress(&p, g_acc); float* accbuf = (float*)p;
    cudaGetSymbolAddress(&p, g_h1);  float* h1buf  = (float*)p;
    cudaGetSymbolAddress(&p, g_as);  float* asb    = (float*)p;
    cudaGetSymbolAddress(&p, g_ad);  float* adb    = (float*)p;
    cudaGetSymbolAddress(&p, g_e);   float* ebuf   = (float*)p;
    cudaGetSymbolAddress(&p, g_m);   int*   mkey   = (int*)p;
    cudaGetSymbolAddress(&p, g_den); float* denb   = (float*)p;

    // layer 1: z -> h1
    run_layer(z, ei, W1, as1, ad1, b1, hbuf, accbuf, asb, adb, ebuf, mkey, denb, n, ne);
    relu_copy<<<(n * 256 + 255) / 256, 256>>>(accbuf, h1buf, n * 256);

    // layer 2: h1 -> acc (relu fused into head)
    run_layer(h1buf, ei, W2, as2, ad2, b2, hbuf, accbuf, asb, adb, ebuf, mkey, denb, n, ne);

    // head: sigmoid(relu(acc) @ Wh + bh)
    head_kernel<<<(n + 7) / 8, 256>>>(accbuf, Wh, bh, out, n);
}

// round 3
// speedup vs baseline: 1.0041x; 1.0041x over previous
#include <cuda_runtime.h>
#include <cstdint>

#define NMAX 50000
#define EMAX 262144
#define HDIM 256

// ---------------- scratch (no allocations allowed) ----------------
__device__ float g_h[NMAX * HDIM];     // per-type h = x @ W[t]
__device__ float g_acc[NMAX * HDIM];   // per-layer accumulator (sum over types)
__device__ float g_h1[NMAX * HDIM];    // layer-1 output
__device__ float g_as[NMAX];
__device__ float g_ad[NMAX];
__device__ float g_e[EMAX];
__device__ int   g_m[NMAX];
__device__ float g_den[NMAX];

// ---------------- helpers ----------------
__device__ __forceinline__ uint32_t f2tf(float f) {
    uint32_t r;
    asm("cvt.rna.tf32.f32 %0, %1;" : "=r"(r) : "f"(f));
    return r;
}

// monotone int encoding of float for atomicMax-based segment max
__device__ __forceinline__ int fkey(float f) {
    int i = __float_as_int(f);
    return i >= 0 ? i : (i ^ 0x7fffffff);
}
__device__ __forceinline__ float fdec(int k) {
    int i = k >= 0 ? k : (k ^ 0x7fffffff);
    return __int_as_float(i);
}

// ---------------- GEMM: Hout[n,256] = X[n,256] @ W[256,256], tf32 MMA ----------------
// BM=128, BN=64, BK=32, 256 threads (8 warps: 4 in M x 2 in N), warp tile 32x32
__global__ __launch_bounds__(256) void gemm_tf32(
    const float* __restrict__ X, const float* __restrict__ W,
    float* __restrict__ Hout, int nrows)
{
    __shared__ uint32_t As[128][36];   // [m][k], pad to 36 -> conflict-free frag reads
    __shared__ uint32_t Bs[32][72];    // [k][n], pad to 72 -> conflict-free frag reads
    int tid  = threadIdx.x;
    int lane = tid & 31, warp = tid >> 5;
    int wm = warp >> 1, wn = warp & 1;
    int g  = lane >> 2, tig = lane & 3;
    int bm = blockIdx.x * 128;
    int bn = blockIdx.y * 64;

    float acc[2][4][4];
#pragma unroll
    for (int a = 0; a < 2; a++)
#pragma unroll
        for (int b = 0; b < 4; b++)
#pragma unroll
            for (int c = 0; c < 4; c++) acc[a][b][c] = 0.f;

    for (int k0 = 0; k0 < 256; k0 += 32) {
        // stage A tile 128x32
#pragma unroll
        for (int p = 0; p < 4; p++) {
            int r  = (tid >> 3) + p * 32;
            int c4 = (tid & 7) * 4;
            int gr = bm + r;
            float4 v = make_float4(0.f, 0.f, 0.f, 0.f);
            if (gr < nrows) v = *(const float4*)(X + (size_t)gr * 256 + k0 + c4);
            As[r][c4 + 0] = f2tf(v.x); As[r][c4 + 1] = f2tf(v.y);
            As[r][c4 + 2] = f2tf(v.z); As[r][c4 + 3] = f2tf(v.w);
        }
        // stage B tile 32x64
#pragma unroll
        for (int p = 0; p < 2; p++) {
            int r  = (tid >> 4) + p * 16;
            int c4 = (tid & 15) * 4;
            float4 v = *(const float4*)(W + (size_t)(k0 + r) * 256 + bn + c4);
            Bs[r][c4 + 0] = f2tf(v.x); Bs[r][c4 + 1] = f2tf(v.y);
            Bs[r][c4 + 2] = f2tf(v.z); Bs[r][c4 + 3] = f2tf(v.w);
        }
        __syncthreads();

#pragma unroll
        for (int kk = 0; kk < 32; kk += 8) {
            uint32_t a[2][4], b[4][2];
#pragma unroll
            for (int mm = 0; mm < 2; mm++) {
                int row = wm * 32 + mm * 16 + g;
                a[mm][0] = As[row][kk + tig];
                a[mm][1] = As[row + 8][kk + tig];
                a[mm][2] = As[row][kk + tig + 4];
                a[mm][3] = As[row + 8][kk + tig + 4];
            }
#pragma unroll
            for (int nn = 0; nn < 4; nn++) {
                int col = wn * 32 + nn * 8 + g;
                b[nn][0] = Bs[kk + tig][col];
                b[nn][1] = Bs[kk + tig + 4][col];
            }
#pragma unroll
            for (int mm = 0; mm < 2; mm++)
#pragma unroll
                for (int nn = 0; nn < 4; nn++)
                    asm volatile(
                        "mma.sync.aligned.m16n8k8.row.col.f32.tf32.tf32.f32 "
                        "{%0,%1,%2,%3}, {%4,%5,%6,%7}, {%8,%9}, {%0,%1,%2,%3};"
                        : "+f"(acc[mm][nn][0]), "+f"(acc[mm][nn][1]),
                          "+f"(acc[mm][nn][2]), "+f"(acc[mm][nn][3])
                        : "r"(a[mm][0]), "r"(a[mm][1]), "r"(a[mm][2]), "r"(a[mm][3]),
                          "r"(b[nn][0]), "r"(b[nn][1]));
        }
        __syncthreads();
    }

#pragma unroll
    for (int mm = 0; mm < 2; mm++)
#pragma unroll
        for (int nn = 0; nn < 4; nn++) {
            int row = bm + wm * 32 + mm * 16 + g;
            int col = bn + wn * 32 + nn * 8 + 2 * tig;
            if (row < nrows)
                *(float2*)(Hout + (size_t)row * 256 + col) =
                    make_float2(acc[mm][nn][0], acc[mm][nn][1]);
            if (row + 8 < nrows)
                *(float2*)(Hout + (size_t)(row + 8) * 256 + col) =
                    make_float2(acc[mm][nn][2], acc[mm][nn][3]);
        }
}

// ---------------- per-row dots: a_src[i]=h_i . a_s ; a_dst[i]=h_i . a_d ----------------
__global__ __launch_bounds__(256) void rowdot(
    const float* __restrict__ h, const float* __restrict__ avs,
    const float* __restrict__ avd, float* __restrict__ outs,
    float* __restrict__ outd, int nrows)
{
    int w    = (blockIdx.x * blockDim.x + threadIdx.x) >> 5;
    int lane = threadIdx.x & 31;
    if (w >= nrows) return;
    const float4* hr = (const float4*)(h + (size_t)w * 256);
    const float4* s4 = (const float4*)avs;
    const float4* d4 = (const float4*)avd;
    float ss = 0.f, sd = 0.f;
#pragma unroll
    for (int j = 0; j < 2; j++) {
        int idx  = lane + j * 32;
        float4 v = hr[idx];
        float4 a = __ldg(&s4[idx]);
        float4 b = __ldg(&d4[idx]);
        ss += v.x * a.x + v.y * a.y + v.z * a.z + v.w * a.w;
        sd += v.x * b.x + v.y * b.y + v.z * b.z + v.w * b.w;
    }
#pragma unroll
    for (int o = 16; o; o >>= 1) {
        ss += __shfl_xor_sync(0xffffffffu, ss, o);
        sd += __shfl_xor_sync(0xffffffffu, sd, o);
    }
    if (lane == 0) { outs[w] = ss; outd[w] = sd; }
}

// ---------------- init kernels ----------------
__global__ void init_md(int* __restrict__ mk, float* __restrict__ den, int n) {
    int i = blockIdx.x * blockDim.x + threadIdx.x;
    if (i < n) { mk[i] = (int)0x80000000; den[i] = 0.f; }
}

__global__ void init_acc(float* __restrict__ acc, const float* __restrict__ b, int n) {
    int i = blockIdx.x * blockDim.x + threadIdx.x;
    if (i < n * 256) {
        int c = i & 255;
        acc[i] = b[c] + b[256 + c] + b[512 + c];
    }
}

// ---------------- edge passes ----------------
__global__ void edge_score(const int* __restrict__ src, const int* __restrict__ dst,
                           const float* __restrict__ as_, const float* __restrict__ ad_,
                           float* __restrict__ e, int* __restrict__ mk, int ne)
{
    int i = blockIdx.x * blockDim.x + threadIdx.x;
    if (i >= ne) return;
    float v = as_[src[i]] + ad_[dst[i]];
    v = v > 0.f ? v : 0.2f * v;   // leaky_relu 0.2
    e[i] = v;
    atomicMax(&mk[dst[i]], fkey(v));
}

__global__ void edge_exp(const int* __restrict__ dst, float* __restrict__ e,
                         const int* __restrict__ mk, float* __restrict__ den, int ne)
{
    int i = blockIdx.x * blockDim.x + threadIdx.x;
    if (i >= ne) return;
    int d   = dst[i];
    float m = fdec(mk[d]);
    float x = __expf(e[i] - m);
    e[i] = x;
    atomicAdd(&den[d], x);
}

// one warp per edge: acc[dst] += alpha * h[src]  (vector L2 reduction)
__global__ __launch_bounds__(256) void edge_scatter(
    const int* __restrict__ src, const int* __restrict__ dst,
    const float* __restrict__ ex, const float* __restrict__ den,
    const float* __restrict__ h, float* __restrict__ acc, int ne)
{
    int w    = (blockIdx.x * blockDim.x + threadIdx.x) >> 5;
    int lane = threadIdx.x & 31;
    if (w >= ne) return;
    int s = src[w], d = dst[w];
    float alpha = ex[w] / den[d];
    const float4* hr = (const float4*)(h + (size_t)s * 256);
    float* ar = acc + (size_t)d * 256;
#pragma unroll
    for (int j = 0; j < 2; j++) {
        int idx  = lane + j * 32;
        float4 v = hr[idx];
        asm volatile("red.global.add.v4.f32 [%0], {%1,%2,%3,%4};"
                     :: "l"(ar + idx * 4),
                        "f"(v.x * alpha), "f"(v.y * alpha),
                        "f"(v.z * alpha), "f"(v.w * alpha)
                     : "memory");
    }
}

// ---------------- pointwise / head ----------------
__global__ void relu_copy(const float* __restrict__ acc, float* __restrict__ y, int total) {
    int i = blockIdx.x * blockDim.x + threadIdx.x;
    if (i < total) y[i] = fmaxf(acc[i], 0.f);
}

__global__ __launch_bounds__(256) void head_kernel(
    const float* __restrict__ acc, const float* __restrict__ Wh,
    const float* __restrict__ bh, float* __restrict__ out, int nrows)
{
    int w    = (blockIdx.x * blockDim.x + threadIdx.x) >> 5;
    int lane = threadIdx.x & 31;
    if (w >= nrows) return;
    const float4* ar = (const float4*)(acc + (size_t)w * 256);
    const float4* wh = (const float4*)Wh;
    float s = 0.f;
#pragma unroll
    for (int j = 0; j < 2; j++) {
        int idx  = lane + j * 32;
        float4 v = ar[idx];
        float4 q = __ldg(&wh[idx]);
        s += fmaxf(v.x, 0.f) * q.x + fmaxf(v.y, 0.f) * q.y +
             fmaxf(v.z, 0.f) * q.z + fmaxf(v.w, 0.f) * q.w;
    }
#pragma unroll
    for (int o = 16; o; o >>= 1) s += __shfl_xor_sync(0xffffffffu, s, o);
    if (lane == 0) out[w] = 1.f / (1.f + __expf(-(s + bh[0])));
}

// ---------------- host orchestration ----------------
static void run_layer(const float* x, const int* ei,
                      const float* W, const float* av_s, const float* av_d,
                      const float* bias,
                      float* hbuf, float* accbuf, float* asb, float* adb,
                      float* ebuf, int* mkey, float* denb, int n, int ne)
{
    init_acc<<<(n * 256 + 255) / 256, 256>>>(accbuf, bias, n);
    for (int t = 0; t < 3; t++) {
        gemm_tf32<<<dim3((n + 127) / 128, 4), 256>>>(x, W + (size_t)t * 256 * 256, hbuf, n);
        rowdot<<<(n + 7) / 8, 256>>>(hbuf, av_s + t * 256, av_d + t * 256, asb, adb, n);
        init_md<<<(n + 255) / 256, 256>>>(mkey, denb, n);
        const int* src = ei + (size_t)t * 2 * ne;
        const int* dst = src + ne;
        edge_score<<<(ne + 255) / 256, 256>>>(src, dst, asb, adb, ebuf, mkey, ne);
        edge_exp<<<(ne + 255) / 256, 256>>>(dst, ebuf, mkey, denb, ne);
        edge_scatter<<<(ne + 7) / 8, 256>>>(src, dst, ebuf, denb, hbuf, accbuf, ne);
    }
}

extern "C" void kernel_launch(void* const* d_in, const int* in_sizes, int n_in,
                              void* d_out, int out_size)
{
    const float* z   = (const float*)d_in[0];
    const int*   ei  = (const int*)d_in[1];
    const float* W1  = (const float*)d_in[2];
    const float* as1 = (const float*)d_in[3];
    const float* ad1 = (const float*)d_in[4];
    const float* b1  = (const float*)d_in[5];
    const float* W2  = (const float*)d_in[6];
    const float* as2 = (const float*)d_in[7];
    const float* ad2 = (const float*)d_in[8];
    const float* b2  = (const float*)d_in[9];
    const float* Wh  = (const float*)d_in[10];
    const float* bh  = (const float*)d_in[11];
    float* out = (float*)d_out;

    int n  = in_sizes[0] / 256;   // 50000
    int ne = in_sizes[1] / 6;     // 250000

    void* p;
    cudaGetSymbolAddress(&p, g_h);   float* hbuf   = (float*)p;
    cudaGetSymbolAddress(&p, g_acc); float* accbuf = (float*)p;
    cudaGetSymbolAddress(&p, g_h1);  float* h1buf  = (float*)p;
    cudaGetSymbolAddress(&p, g_as);  float* asb    = (float*)p;
    cudaGetSymbolAddress(&p, g_ad);  float* adb    = (float*)p;
    cudaGetSymbolAddress(&p, g_e);   float* ebuf   = (float*)p;
    cudaGetSymbolAddress(&p, g_m);   int*   mkey   = (int*)p;
    cudaGetSymbolAddress(&p, g_den); float* denb   = (float*)p;

    // layer 1: z -> h1
    run_layer(z, ei, W1, as1, ad1, b1, hbuf, accbuf, asb, adb, ebuf, mkey, denb, n, ne);
    relu_copy<<<(n * 256 + 255) / 256, 256>>>(accbuf, h1buf, n * 256);

    // layer 2: h1 -> acc (relu fused into head)
    run_layer(h1buf, ei, W2, as2, ad2, b2, hbuf, accbuf, asb, adb, ebuf, mkey, denb, n, ne);

    // head: sigmoid(relu(acc) @ Wh + bh)
    head_kernel<<<(n + 7) / 8, 256>>>(accbuf, Wh, bh, out, n);
}

// round 4
// speedup vs baseline: 1.3779x; 1.3723x over previous
#include <cuda_runtime.h>
#include <cstdint>

#define NMAX 50048
#define EMAX 250112
#define TT 3

// ---------------- scratch (static device globals; no allocation) ----------------
__device__ float g_hcat[TT * NMAX * 256];   // per-type h = x @ W[t], [t][node][256]
__device__ float g_h1[NMAX * 256];          // layer-1 output
__device__ float g_as[TT * NMAX];           // a_src per type
__device__ float g_ad[TT * NMAX];           // a_dst per type
__device__ float g_ws[TT * 256];            // W_t @ a_s
__device__ float g_wd[TT * 256];            // W_t @ a_d
__device__ int   g_cnt[TT * NMAX];          // in-degree counts
__device__ int   g_cur[TT * NMAX];          // fill cursors
__device__ int   g_off[TT * (NMAX + 1)];    // CSR offsets (by dst)
__device__ int   g_csr[TT * EMAX];          // CSR: src node per slot

// ---------------- small float4 helpers ----------------
__device__ __forceinline__ float4 f4add(float4 a, float4 b) {
    return make_float4(a.x + b.x, a.y + b.y, a.z + b.z, a.w + b.w);
}
__device__ __forceinline__ float4 f4fma(float4 a, float s, float4 c) {
    return make_float4(fmaf(a.x, s, c.x), fmaf(a.y, s, c.y),
                       fmaf(a.z, s, c.z), fmaf(a.w, s, c.w));
}
__device__ __forceinline__ float4 f4relu(float4 a) {
    return make_float4(fmaxf(a.x, 0.f), fmaxf(a.y, 0.f),
                       fmaxf(a.z, 0.f), fmaxf(a.w, 0.f));
}

// ============ fused GEMM: Hcat[t][n][256] = X[n][256] @ W[t][256][256] ============
// BM=128, BN=64, BK=32, 2-stage cp.async pipeline, tf32 MMA on raw fp32 bits.
// grid = (ceil(n/128), 12): blockIdx.y -> (t = y>>2, ntile = (y&3)*64)
__global__ __launch_bounds__(256) void gemm_fused(
    const float* __restrict__ X, const float* __restrict__ W,
    float* __restrict__ Hcat, int nrows)
{
    __shared__ uint32_t As[2][128 * 36];   // pitch 36 (144B, 16B aligned, conflict-free)
    __shared__ uint32_t Bs[2][32 * 72];    // pitch 72
    int tid  = threadIdx.x;
    int lane = tid & 31, warp = tid >> 5;
    int wm = warp >> 1, wn = warp & 1;
    int g  = lane >> 2, tig = lane & 3;
    int bm  = blockIdx.x * 128;
    int t   = blockIdx.y >> 2;
    int bnl = (blockIdx.y & 3) * 64;
    const float* Wt = W + (size_t)t * 65536;
    float* Hout = Hcat + (size_t)t * nrows * 256;

    auto stage = [&](int st, int k0) {
#pragma unroll
        for (int p = 0; p < 4; p++) {            // A: 1024 x 16B
            int i = tid + p * 256;
            int r = i >> 3, grp = i & 7;
            uint32_t d = (uint32_t)__cvta_generic_to_shared(&As[st][r * 36 + grp * 4]);
            const float* s = X + (size_t)(bm + r) * 256 + k0 + grp * 4;
            int sz = (bm + r) < nrows ? 16 : 0;  // zero-fill OOB rows
            asm volatile("cp.async.ca.shared.global [%0], [%1], 16, %2;"
                         :: "r"(d), "l"(s), "r"(sz));
        }
#pragma unroll
        for (int p = 0; p < 2; p++) {            // B: 512 x 16B
            int i = tid + p * 256;
            int r = i >> 4, grp = i & 15;
            uint32_t d = (uint32_t)__cvta_generic_to_shared(&Bs[st][r * 72 + grp * 4]);
            const float* s = Wt + (size_t)(k0 + r) * 256 + bnl + grp * 4;
            asm volatile("cp.async.ca.shared.global [%0], [%1], 16;"
                         :: "r"(d), "l"(s));
        }
        asm volatile("cp.async.commit_group;");
    };

    float acc[2][4][4];
#pragma unroll
    for (int a = 0; a < 2; a++)
#pragma unroll
        for (int b = 0; b < 4; b++)
#pragma unroll
            for (int c = 0; c < 4; c++) acc[a][b][c] = 0.f;

    stage(0, 0);
    for (int k0 = 0; k0 < 256; k0 += 32) {
        int cur = (k0 >> 5) & 1;
        if (k0 + 32 < 256) {
            stage(cur ^ 1, k0 + 32);
            asm volatile("cp.async.wait_group 1;");
        } else {
            asm volatile("cp.async.wait_group 0;");
        }
        __syncthreads();

#pragma unroll
        for (int kk = 0; kk < 32; kk += 8) {
            uint32_t a[2][4], b[4][2];
#pragma unroll
            for (int mm = 0; mm < 2; mm++) {
                int row = wm * 32 + mm * 16 + g;
                a[mm][0] = As[cur][row * 36 + kk + tig];
                a[mm][1] = As[cur][(row + 8) * 36 + kk + tig];
                a[mm][2] = As[cur][row * 36 + kk + tig + 4];
                a[mm][3] = As[cur][(row + 8) * 36 + kk + tig + 4];
            }
#pragma unroll
            for (int nn = 0; nn < 4; nn++) {
                int col = wn * 32 + nn * 8 + g;
                b[nn][0] = Bs[cur][(kk + tig) * 72 + col];
                b[nn][1] = Bs[cur][(kk + tig + 4) * 72 + col];
            }
#pragma unroll
            for (int mm = 0; mm < 2; mm++)
#pragma unroll
                for (int nn = 0; nn < 4; nn++)
                    asm volatile(
                        "mma.sync.aligned.m16n8k8.row.col.f32.tf32.tf32.f32 "
                        "{%0,%1,%2,%3}, {%4,%5,%6,%7}, {%8,%9}, {%0,%1,%2,%3};"
                        : "+f"(acc[mm][nn][0]), "+f"(acc[mm][nn][1]),
                          "+f"(acc[mm][nn][2]), "+f"(acc[mm][nn][3])
                        : "r"(a[mm][0]), "r"(a[mm][1]), "r"(a[mm][2]), "r"(a[mm][3]),
                          "r"(b[nn][0]), "r"(b[nn][1]));
        }
        __syncthreads();
    }

#pragma unroll
    for (int mm = 0; mm < 2; mm++)
#pragma unroll
        for (int nn = 0; nn < 4; nn++) {
            int row = bm + wm * 32 + mm * 16 + g;
            int col = bnl + wn * 32 + nn * 8 + 2 * tig;
            if (row < nrows)
                *(float2*)(Hout + (size_t)row * 256 + col) =
                    make_float2(acc[mm][nn][0], acc[mm][nn][1]);
            if (row + 8 < nrows)
                *(float2*)(Hout + (size_t)(row + 8) * 256 + col) =
                    make_float2(acc[mm][nn][2], acc[mm][nn][3]);
        }
}

// ============ wvec: ws[t][r] = W[t][r][:].a_s[t],  wd likewise (warp per (t,r)) ============
__global__ __launch_bounds__(256) void wvec_kernel(
    const float* __restrict__ W, const float* __restrict__ av_s,
    const float* __restrict__ av_d, float* __restrict__ ws, float* __restrict__ wd)
{
    int w    = (blockIdx.x * blockDim.x + threadIdx.x) >> 5;   // 0..767
    int lane = threadIdx.x & 31;
    if (w >= TT * 256) return;
    int t = w >> 8, r = w & 255;
    const float4* row = (const float4*)(W + (size_t)t * 65536 + (size_t)r * 256);
    const float4* s4  = (const float4*)(av_s + t * 256);
    const float4* d4  = (const float4*)(av_d + t * 256);
    float ss = 0.f, sd = 0.f;
#pragma unroll
    for (int j = 0; j < 2; j++) {
        int idx  = lane + j * 32;
        float4 v = row[idx];
        float4 a = __ldg(&s4[idx]);
        float4 b = __ldg(&d4[idx]);
        ss += v.x * a.x + v.y * a.y + v.z * a.z + v.w * a.w;
        sd += v.x * b.x + v.y * b.y + v.z * b.z + v.w * b.w;
    }
#pragma unroll
    for (int o = 16; o; o >>= 1) {
        ss += __shfl_xor_sync(0xffffffffu, ss, o);
        sd += __shfl_xor_sync(0xffffffffu, sd, o);
    }
    if (lane == 0) { ws[w] = ss; wd[w] = sd; }
}

// ============ rowdot6: one pass over X computing all 6 scores (warp per node) ============
__global__ __launch_bounds__(256) void rowdot6(
    const float* __restrict__ X, const float* __restrict__ ws,
    const float* __restrict__ wd, float* __restrict__ outs,
    float* __restrict__ outd, int n)
{
    int w    = (blockIdx.x * blockDim.x + threadIdx.x) >> 5;
    int lane = threadIdx.x & 31;
    if (w >= n) return;
    const float4* xr = (const float4*)(X + (size_t)w * 256);
    float ss[TT] = {0.f, 0.f, 0.f}, sd[TT] = {0.f, 0.f, 0.f};
#pragma unroll
    for (int j = 0; j < 2; j++) {
        int idx  = lane + j * 32;
        float4 v = xr[idx];
#pragma unroll
        for (int t = 0; t < TT; t++) {
            float4 a = __ldg(&((const float4*)(ws + t * 256))[idx]);
            float4 b = __ldg(&((const float4*)(wd + t * 256))[idx]);
            ss[t] += v.x * a.x + v.y * a.y + v.z * a.z + v.w * a.w;
            sd[t] += v.x * b.x + v.y * b.y + v.z * b.z + v.w * b.w;
        }
    }
#pragma unroll
    for (int o = 16; o; o >>= 1)
#pragma unroll
        for (int t = 0; t < TT; t++) {
            ss[t] += __shfl_xor_sync(0xffffffffu, ss[t], o);
            sd[t] += __shfl_xor_sync(0xffffffffu, sd[t], o);
        }
    if (lane == 0)
#pragma unroll
        for (int t = 0; t < TT; t++) { outs[t * n + w] = ss[t]; outd[t * n + w] = sd[t]; }
}

// ============ CSR build (once; graph shared by both layers) ============
__global__ void zero_counts(int* __restrict__ cnt, int* __restrict__ cur, int total) {
    int i = blockIdx.x * blockDim.x + threadIdx.x;
    if (i < total) { cnt[i] = 0; cur[i] = 0; }
}

__global__ void hist_kernel(const int* __restrict__ ei, int* __restrict__ cnt,
                            int n, int ne)
{
    int i = blockIdx.x * blockDim.x + threadIdx.x;
    if (i >= TT * ne) return;
    int t = i / ne, e = i - t * ne;
    int d = ei[(size_t)t * 2 * ne + ne + e];
    atomicAdd(&cnt[t * n + d], 1);
}

// exclusive scan of counts -> offsets; one 1024-thread block per type
__global__ __launch_bounds__(1024) void scan_off(
    const int* __restrict__ cnt, int* __restrict__ off, int n)
{
    int t = blockIdx.x;
    const int* c = cnt + t * n;
    int* o = off + t * (n + 1);
    __shared__ int wsum[32];
    __shared__ int carry_sh;
    int tid = threadIdx.x, lane = tid & 31, wid = tid >> 5;
    if (tid == 0) carry_sh = 0;
    __syncthreads();
    for (int base = 0; base < n; base += 1024) {
        int i = base + tid;
        int v = (i < n) ? c[i] : 0;
        int x = v;
#pragma unroll
        for (int o2 = 1; o2 < 32; o2 <<= 1) {
            int y = __shfl_up_sync(0xffffffffu, x, o2);
            if (lane >= o2) x += y;
        }
        if (lane == 31) wsum[wid] = x;
        __syncthreads();
        if (wid == 0) {
            int s = wsum[lane];
#pragma unroll
            for (int o2 = 1; o2 < 32; o2 <<= 1) {
                int y = __shfl_up_sync(0xffffffffu, s, o2);
                if (lane >= o2) s += y;
            }
            wsum[lane] = s;
        }
        __syncthreads();
        int incl  = x + (wid > 0 ? wsum[wid - 1] : 0);
        int carry = carry_sh;
        if (i < n) o[i] = carry + incl - v;
        __syncthreads();
        if (tid == 1023) carry_sh = carry + wsum[31];
        __syncthreads();
    }
    if (threadIdx.x == 0) o[n] = carry_sh;
}

__global__ void fill_kernel(const int* __restrict__ ei, const int* __restrict__ off,
                            int* __restrict__ cur, int* __restrict__ csr,
                            int n, int ne)
{
    int i = blockIdx.x * blockDim.x + threadIdx.x;
    if (i >= TT * ne) return;
    int t = i / ne, e = i - t * ne;
    const int* base = ei + (size_t)t * 2 * ne;
    int s = base[e], d = base[ne + e];
    int pos = off[t * (n + 1) + d] + atomicAdd(&cur[t * n + d], 1);
    csr[t * ne + pos] = s;
}

// ============ fused softmax + aggregate + bias + relu (+ head) : warp per dst ============
// mode 0: outrow[i] = relu(sum_t GAT_t(i) + sum_t bias_t)
// mode 1: headout[i] = sigmoid(relu(...) . Wh + bh)
__global__ __launch_bounds__(256) void agg_kernel(
    const int* __restrict__ off, const int* __restrict__ csr,
    const float* __restrict__ hcat, const float* __restrict__ asb,
    const float* __restrict__ adb, const float* __restrict__ bias,
    float* __restrict__ outrow, const float* __restrict__ Wh,
    const float* __restrict__ bh, float* __restrict__ headout,
    int mode, int n, int ne)
{
    int w    = (blockIdx.x * blockDim.x + threadIdx.x) >> 5;
    int lane = threadIdx.x & 31;
    if (w >= n) return;

    float4 a0 = make_float4(0.f, 0.f, 0.f, 0.f);
    float4 a1 = make_float4(0.f, 0.f, 0.f, 0.f);

#pragma unroll
    for (int t = 0; t < TT; t++) {
        int o0 = off[t * (n + 1) + w];
        int deg = off[t * (n + 1) + w + 1] - o0;
        if (deg == 0) continue;
        float adt = adb[t * n + w];
        const float* ht   = hcat + (size_t)t * n * 256;
        const float* ast  = asb + t * n;
        const int*   srcs = csr + (size_t)t * ne + o0;
        float4 t0 = make_float4(0.f, 0.f, 0.f, 0.f);
        float4 t1 = make_float4(0.f, 0.f, 0.f, 0.f);
        float den = 0.f;
        for (int base = 0; base < deg; base += 32) {
            int m = min(32, deg - base);
            int   sj = 0;
            float ex = 0.f;
            if (lane < m) {
                sj = srcs[base + lane];
                float e = ast[sj] + adt;
                e = e > 0.f ? e : 0.2f * e;        // leaky_relu 0.2
                ex = __expf(e);                     // shift-invariant: no max needed
            }
            float s = ex;
#pragma unroll
            for (int o = 16; o; o >>= 1) s += __shfl_xor_sync(0xffffffffu, s, o);
            den += s;
            for (int j = 0; j < m; j++) {
                int   sn = __shfl_sync(0xffffffffu, sj, j);
                float wt = __shfl_sync(0xffffffffu, ex, j);
                const float4* hr = (const float4*)(ht + (size_t)sn * 256);
                t0 = f4fma(hr[lane], wt, t0);
                t1 = f4fma(hr[lane + 32], wt, t1);
            }
        }
        float inv = 1.f / den;
        a0 = f4fma(t0, inv, a0);
        a1 = f4fma(t1, inv, a1);
    }

    // bias sum over the 3 types, then relu
    const float4* bb = (const float4*)bias;   // [3][256] = 192 float4
    float4 b0 = f4add(f4add(__ldg(&bb[lane]), __ldg(&bb[64 + lane])), __ldg(&bb[128 + lane]));
    float4 b1 = f4add(f4add(__ldg(&bb[lane + 32]), __ldg(&bb[96 + lane])), __ldg(&bb[160 + lane]));
    float4 r0 = f4relu(f4add(a0, b0));
    float4 r1 = f4relu(f4add(a1, b1));

    if (mode == 0) {
        float4* orow = (float4*)(outrow + (size_t)w * 256);
        orow[lane]      = r0;
        orow[lane + 32] = r1;
    } else {
        const float4* wh = (const float4*)Wh;
        float4 q0 = __ldg(&wh[lane]);
        float4 q1 = __ldg(&wh[lane + 32]);
        float s = r0.x * q0.x + r0.y * q0.y + r0.z * q0.z + r0.w * q0.w +
                  r1.x * q1.x + r1.y * q1.y + r1.z * q1.z + r1.w * q1.w;
#pragma unroll
        for (int o = 16; o; o >>= 1) s += __shfl_xor_sync(0xffffffffu, s, o);
        if (lane == 0) headout[w] = 1.f / (1.f + __expf(-(s + bh[0])));
    }
}

// ---------------- host orchestration ----------------
extern "C" void kernel_launch(void* const* d_in, const int* in_sizes, int n_in,
                              void* d_out, int out_size)
{
    const float* z   = (const float*)d_in[0];
    const int*   ei  = (const int*)d_in[1];
    const float* W1  = (const float*)d_in[2];
    const float* as1 = (const float*)d_in[3];
    const float* ad1 = (const float*)d_in[4];
    const float* b1  = (const float*)d_in[5];
    const float* W2  = (const float*)d_in[6];
    const float* as2 = (const float*)d_in[7];
    const float* ad2 = (const float*)d_in[8];
    const float* b2  = (const float*)d_in[9];
    const float* Wh  = (const float*)d_in[10];
    const float* bh  = (const float*)d_in[11];
    float* out = (float*)d_out;

    int n  = in_sizes[0] / 256;   // 50000
    int ne = in_sizes[1] / 6;     // 250000

    void* p;
    cudaGetSymbolAddress(&p, g_hcat); float* hcat = (float*)p;
    cudaGetSymbolAddress(&p, g_h1);   float* h1   = (float*)p;
    cudaGetSymbolAddress(&p, g_as);   float* asb  = (float*)p;
    cudaGetSymbolAddress(&p, g_ad);   float* adb  = (float*)p;
    cudaGetSymbolAddress(&p, g_ws);   float* ws   = (float*)p;
    cudaGetSymbolAddress(&p, g_wd);   float* wd   = (float*)p;
    cudaGetSymbolAddress(&p, g_cnt);  int*   cnt  = (int*)p;
    cudaGetSymbolAddress(&p, g_cur);  int*   cur  = (int*)p;
    cudaGetSymbolAddress(&p, g_off);  int*   off  = (int*)p;
    cudaGetSymbolAddress(&p, g_csr);  int*   csr  = (int*)p;

    // ---- CSR build (graph identical across both layers) ----
    zero_counts<<<(TT * n + 255) / 256, 256>>>(cnt, cur, TT * n);
    hist_kernel<<<(TT * ne + 255) / 256, 256>>>(ei, cnt, n, ne);
    scan_off<<<TT, 1024>>>(cnt, off, n);
    fill_kernel<<<(TT * ne + 255) / 256, 256>>>(ei, off, cur, csr, n, ne);

    dim3 ggrid((n + 127) / 128, 12);

    // ---- layer 1: z -> h1 ----
    wvec_kernel<<<(TT * 256 + 7) / 8, 256>>>(W1, as1, ad1, ws, wd);
    gemm_fused<<<ggrid, 256>>>(z, W1, hcat, n);
    rowdot6<<<(n + 7) / 8, 256>>>(z, ws, wd, asb, adb, n);
    agg_kernel<<<(n + 7) / 8, 256>>>(off, csr, hcat, asb, adb, b1,
                                     h1, Wh, bh, out, 0, n, ne);

    // ---- layer 2: h1 -> head (fused) ----
    wvec_kernel<<<(TT * 256 + 7) / 8, 256>>>(W2, as2, ad2, ws, wd);
    gemm_fused<<<ggrid, 256>>>(h1, W2, hcat, n);
    rowdot6<<<(n + 7) / 8, 256>>>(h1, ws, wd, asb, adb, n);
    agg_kernel<<<(n + 7) / 8, 256>>>(off, csr, hcat, asb, adb, b2,
                                     h1 /*unused*/, Wh, bh, out, 1, n, ne);
}

// round 8
// speedup vs baseline: 1.5197x; 1.1029x over previous
#include <cuda_runtime.h>
#include <cstdint>

#define NMAX 50048
#define EMAX 250112
#define TT 3

// ---------------- scratch (static device globals; no allocation) ----------------
__device__ float g_hcat[TT * NMAX * 256];   // per-type h = x @ W[t]
__device__ float g_h1[NMAX * 256];          // layer-1 output
__device__ float g_as[TT * NMAX];
__device__ float g_ad[TT * NMAX];
__device__ float g_ws[TT * 256];
__device__ float g_wd[TT * 256];
__device__ int   g_cnt[TT * NMAX];
__device__ int   g_cur[TT * NMAX];
__device__ int   g_off[TT * (NMAX + 1)];
__device__ int   g_csr[TT * EMAX];

// ---------------- small float4 helpers ----------------
__device__ __forceinline__ float4 f4add(float4 a, float4 b) {
    return make_float4(a.x + b.x, a.y + b.y, a.z + b.z, a.w + b.w);
}
__device__ __forceinline__ float4 f4fma(float4 a, float s, float4 c) {
    return make_float4(fmaf(a.x, s, c.x), fmaf(a.y, s, c.y),
                       fmaf(a.z, s, c.z), fmaf(a.w, s, c.w));
}
__device__ __forceinline__ float4 f4relu(float4 a) {
    return make_float4(fmaxf(a.x, 0.f), fmaxf(a.y, 0.f),
                       fmaxf(a.z, 0.f), fmaxf(a.w, 0.f));
}

// ============ fused GEMM: Hcat[t][n][256] = X[n][256] @ W[t][256][256] ============
// BM=128, BN=128, BK=32, 2-stage cp.async, tf32 mma.sync on raw fp32 bits.
// 8 warps: 4 in M x 2 in N, warp tile 32x64. grid = (ceil(n/128), 6):
//   t = blockIdx.y >> 1, bn = (blockIdx.y & 1) * 128.
// Dynamic smem: As[2][128*36] + Bs[2][32*136] u32 = 71680 B.
#define APITCH 36
#define BPITCH 136
#define ASTG   (128 * APITCH)
#define BSTG   (32 * BPITCH)
#define GSMEM  ((2 * ASTG + 2 * BSTG) * 4)

__global__ __launch_bounds__(256) void gemm_fused(
    const float* __restrict__ X, const float* __restrict__ W,
    float* __restrict__ Hcat, int nrows)
{
    extern __shared__ uint32_t dsm[];
    uint32_t* As = dsm;              // [2][ASTG]
    uint32_t* Bs = dsm + 2 * ASTG;   // [2][BSTG]

    int tid  = threadIdx.x;
    int lane = tid & 31, warp = tid >> 5;
    int wm = warp >> 1, wn = warp & 1;
    int g  = lane >> 2, tig = lane & 3;
    int bm = blockIdx.x * 128;
    int t  = blockIdx.y >> 1;
    int bn = (blockIdx.y & 1) * 128;
    const float* Wt = W + (size_t)t * 65536;
    float* Hout = Hcat + (size_t)t * nrows * 256;

    auto stage = [&](int st, int k0) {
#pragma unroll
        for (int p = 0; p < 4; p++) {            // A: 128 rows x 8 groups of 16B
            int i = tid + p * 256;
            int r = i >> 3, grp = i & 7;
            uint32_t d = (uint32_t)__cvta_generic_to_shared(
                &As[st * ASTG + r * APITCH + grp * 4]);
            const float* s = X + (size_t)(bm + r) * 256 + k0 + grp * 4;
            int sz = (bm + r) < nrows ? 16 : 0;
            asm volatile("cp.async.ca.shared.global [%0], [%1], 16, %2;"
                         :: "r"(d), "l"(s), "r"(sz));
        }
#pragma unroll
        for (int p = 0; p < 4; p++) {            // B: 32 rows x 32 groups of 16B
            int i = tid + p * 256;
            int r = i >> 5, grp = i & 31;
            uint32_t d = (uint32_t)__cvta_generic_to_shared(
                &Bs[st * BSTG + r * BPITCH + grp * 4]);
            const float* s = Wt + (size_t)(k0 + r) * 256 + bn + grp * 4;
            asm volatile("cp.async.ca.shared.global [%0], [%1], 16;"
                         :: "r"(d), "l"(s));
        }
        asm volatile("cp.async.commit_group;");
    };

    float acc[2][8][4];
#pragma unroll
    for (int a = 0; a < 2; a++)
#pragma unroll
        for (int b = 0; b < 8; b++)
#pragma unroll
            for (int c = 0; c < 4; c++) acc[a][b][c] = 0.f;

    stage(0, 0);
    for (int k0 = 0; k0 < 256; k0 += 32) {
        int cur = (k0 >> 5) & 1;
        if (k0 + 32 < 256) {
            stage(cur ^ 1, k0 + 32);
            asm volatile("cp.async.wait_group 1;");
        } else {
            asm volatile("cp.async.wait_group 0;");
        }
        __syncthreads();

        const uint32_t* Ac = As + cur * ASTG;
        const uint32_t* Bc = Bs + cur * BSTG;
#pragma unroll
        for (int kk = 0; kk < 32; kk += 8) {
            uint32_t a[2][4], b[8][2];
#pragma unroll
            for (int mm = 0; mm < 2; mm++) {
                int row = wm * 32 + mm * 16 + g;
                a[mm][0] = Ac[row * APITCH + kk + tig];
                a[mm][1] = Ac[(row + 8) * APITCH + kk + tig];
                a[mm][2] = Ac[row * APITCH + kk + tig + 4];
                a[mm][3] = Ac[(row + 8) * APITCH + kk + tig + 4];
            }
#pragma unroll
            for (int nn = 0; nn < 8; nn++) {
                int col = wn * 64 + nn * 8 + g;
                b[nn][0] = Bc[(kk + tig) * BPITCH + col];
                b[nn][1] = Bc[(kk + tig + 4) * BPITCH + col];
            }
#pragma unroll
            for (int mm = 0; mm < 2; mm++)
#pragma unroll
                for (int nn = 0; nn < 8; nn++)
                    asm volatile(
                        "mma.sync.aligned.m16n8k8.row.col.f32.tf32.tf32.f32 "
                        "{%0,%1,%2,%3}, {%4,%5,%6,%7}, {%8,%9}, {%0,%1,%2,%3};"
                        : "+f"(acc[mm][nn][0]), "+f"(acc[mm][nn][1]),
                          "+f"(acc[mm][nn][2]), "+f"(acc[mm][nn][3])
                        : "r"(a[mm][0]), "r"(a[mm][1]), "r"(a[mm][2]), "r"(a[mm][3]),
                          "r"(b[nn][0]), "r"(b[nn][1]));
        }
        __syncthreads();
    }

#pragma unroll
    for (int mm = 0; mm < 2; mm++)
#pragma unroll
        for (int nn = 0; nn < 8; nn++) {
            int row = bm + wm * 32 + mm * 16 + g;
            int col = bn + wn * 64 + nn * 8 + 2 * tig;
            if (row < nrows)
                *(float2*)(Hout + (size_t)row * 256 + col) =
                    make_float2(acc[mm][nn][0], acc[mm][nn][1]);
            if (row + 8 < nrows)
                *(float2*)(Hout + (size_t)(row + 8) * 256 + col) =
                    make_float2(acc[mm][nn][2], acc[mm][nn][3]);
        }
}

// ============ wvec: ws[t][r] = W[t][r][:].a_s[t]  (warp per (t,r)) ============
__global__ __launch_bounds__(256) void wvec_kernel(
    const float* __restrict__ W, const float* __restrict__ av_s,
    const float* __restrict__ av_d, float* __restrict__ ws, float* __restrict__ wd)
{
    int w    = (blockIdx.x * blockDim.x + threadIdx.x) >> 5;
    int lane = threadIdx.x & 31;
    if (w >= TT * 256) return;
    int t = w >> 8, r = w & 255;
    const float4* row = (const float4*)(W + (size_t)t * 65536 + (size_t)r * 256);
    const float4* s4  = (const float4*)(av_s + t * 256);
    const float4* d4  = (const float4*)(av_d + t * 256);
    float ss = 0.f, sd = 0.f;
#pragma unroll
    for (int j = 0; j < 2; j++) {
        int idx  = lane + j * 32;
        float4 v = row[idx];
        float4 a = __ldg(&s4[idx]);
        float4 b = __ldg(&d4[idx]);
        ss += v.x * a.x + v.y * a.y + v.z * a.z + v.w * a.w;
        sd += v.x * b.x + v.y * b.y + v.z * b.z + v.w * b.w;
    }
#pragma unroll
    for (int o = 16; o; o >>= 1) {
        ss += __shfl_xor_sync(0xffffffffu, ss, o);
        sd += __shfl_xor_sync(0xffffffffu, sd, o);
    }
    if (lane == 0) { ws[w] = ss; wd[w] = sd; }
}

// ============ rowdot6: all 6 attention dots in one pass over X ============
__global__ __launch_bounds__(256) void rowdot6(
    const float* __restrict__ X, const float* __restrict__ ws,
    const float* __restrict__ wd, float* __restrict__ outs,
    float* __restrict__ outd, int n)
{
    int w    = (blockIdx.x * blockDim.x + threadIdx.x) >> 5;
    int lane = threadIdx.x & 31;
    if (w >= n) return;
    const float4* xr = (const float4*)(X + (size_t)w * 256);
    float ss[TT] = {0.f, 0.f, 0.f}, sd[TT] = {0.f, 0.f, 0.f};
#pragma unroll
    for (int j = 0; j < 2; j++) {
        int idx  = lane + j * 32;
        float4 v = xr[idx];
#pragma unroll
        for (int t = 0; t < TT; t++) {
            float4 a = __ldg(&((const float4*)(ws + t * 256))[idx]);
            float4 b = __ldg(&((const float4*)(wd + t * 256))[idx]);
            ss[t] += v.x * a.x + v.y * a.y + v.z * a.z + v.w * a.w;
            sd[t] += v.x * b.x + v.y * b.y + v.z * b.z + v.w * b.w;
        }
    }
#pragma unroll
    for (int o = 16; o; o >>= 1)
#pragma unroll
        for (int t = 0; t < TT; t++) {
            ss[t] += __shfl_xor_sync(0xffffffffu, ss[t], o);
            sd[t] += __shfl_xor_sync(0xffffffffu, sd[t], o);
        }
    if (lane == 0)
#pragma unroll
        for (int t = 0; t < TT; t++) { outs[t * n + w] = ss[t]; outd[t * n + w] = sd[t]; }
}

// ============ CSR build (once; graph shared by both layers) ============
__global__ void zero_counts(int* __restrict__ cnt, int* __restrict__ cur, int total) {
    int i = blockIdx.x * blockDim.x + threadIdx.x;
    if (i < total) { cnt[i] = 0; cur[i] = 0; }
}

__global__ void hist_kernel(const int* __restrict__ ei, int* __restrict__ cnt,
                            int n, int ne)
{
    int i = blockIdx.x * blockDim.x + threadIdx.x;
    if (i >= TT * ne) return;
    int t = i / ne, e = i - t * ne;
    int d = ei[(size_t)t * 2 * ne + ne + e];
    atomicAdd(&cnt[t * n + d], 1);
}

__global__ __launch_bounds__(1024) void scan_off(
    const int* __restrict__ cnt, int* __restrict__ off, int n)
{
    int t = blockIdx.x;
    const int* c = cnt + t * n;
    int* o = off + t * (n + 1);
    __shared__ int wsum[32];
    __shared__ int carry_sh;
    int tid = threadIdx.x, lane = tid & 31, wid = tid >> 5;
    if (tid == 0) carry_sh = 0;
    __syncthreads();
    for (int base = 0; base < n; base += 1024) {
        int i = base + tid;
        int v = (i < n) ? c[i] : 0;
        int x = v;
#pragma unroll
        for (int o2 = 1; o2 < 32; o2 <<= 1) {
            int y = __shfl_up_sync(0xffffffffu, x, o2);
            if (lane >= o2) x += y;
        }
        if (lane == 31) wsum[wid] = x;
        __syncthreads();
        if (wid == 0) {
            int s = wsum[lane];
#pragma unroll
            for (int o2 = 1; o2 < 32; o2 <<= 1) {
                int y = __shfl_up_sync(0xffffffffu, s, o2);
                if (lane >= o2) s += y;
            }
            wsum[lane] = s;
        }
        __syncthreads();
        int incl  = x + (wid > 0 ? wsum[wid - 1] : 0);
        int carry = carry_sh;
        if (i < n) o[i] = carry + incl - v;
        __syncthreads();
        if (tid == 1023) carry_sh = carry + wsum[31];
        __syncthreads();
    }
    if (threadIdx.x == 0) o[n] = carry_sh;
}

__global__ void fill_kernel(const int* __restrict__ ei, const int* __restrict__ off,
                            int* __restrict__ cur, int* __restrict__ csr,
                            int n, int ne)
{
    int i = blockIdx.x * blockDim.x + threadIdx.x;
    if (i >= TT * ne) return;
    int t = i / ne, e = i - t * ne;
    const int* base = ei + (size_t)t * 2 * ne;
    int s = base[e], d = base[ne + e];
    int pos = off[t * (n + 1) + d] + atomicAdd(&cur[t * n + d], 1);
    csr[t * ne + pos] = s;
}

// ============ fused softmax + aggregate + bias + relu (+ head) : warp per dst ============
__global__ __launch_bounds__(256) void agg_kernel(
    const int* __restrict__ off, const int* __restrict__ csr,
    const float* __restrict__ hcat, const float* __restrict__ asb,
    const float* __restrict__ adb, const float* __restrict__ bias,
    float* __restrict__ outrow, const float* __restrict__ Wh,
    const float* __restrict__ bh, float* __restrict__ headout,
    int mode, int n, int ne)
{
    int w    = (blockIdx.x * blockDim.x + threadIdx.x) >> 5;
    int lane = threadIdx.x & 31;
    if (w >= n) return;

    float4 a0 = make_float4(0.f, 0.f, 0.f, 0.f);
    float4 a1 = make_float4(0.f, 0.f, 0.f, 0.f);

#pragma unroll
    for (int t = 0; t < TT; t++) {
        int o0 = off[t * (n + 1) + w];
        int deg = off[t * (n + 1) + w + 1] - o0;
        if (deg == 0) continue;
        float adt = adb[t * n + w];
        const float* ht   = hcat + (size_t)t * n * 256;
        const float* ast  = asb + t * n;
        const int*   srcs = csr + (size_t)t * ne + o0;
        float4 t0 = make_float4(0.f, 0.f, 0.f, 0.f);
        float4 t1 = make_float4(0.f, 0.f, 0.f, 0.f);
        float den = 0.f;
        for (int base = 0; base < deg; base += 32) {
            int m = min(32, deg - base);
            int   sj = 0;
            float ex = 0.f;
            if (lane < m) {
                sj = srcs[base + lane];
                float e = ast[sj] + adt;
                e = e > 0.f ? e : 0.2f * e;      // leaky_relu 0.2
                ex = __expf(e);                   // shift-invariant: no max needed
            }
            float s = ex;
#pragma unroll
            for (int o = 16; o; o >>= 1) s += __shfl_xor_sync(0xffffffffu, s, o);
            den += s;
            for (int j = 0; j < m; j++) {
                int   sn = __shfl_sync(0xffffffffu, sj, j);
                float wt = __shfl_sync(0xffffffffu, ex, j);
                const float4* hr = (const float4*)(ht + (size_t)sn * 256);
                t0 = f4fma(hr[lane], wt, t0);
                t1 = f4fma(hr[lane + 32], wt, t1);
            }
        }
        float inv = 1.f / den;
        a0 = f4fma(t0, inv, a0);
        a1 = f4fma(t1, inv, a1);
    }

    const float4* bb = (const float4*)bias;
    float4 b0 = f4add(f4add(__ldg(&bb[lane]), __ldg(&bb[64 + lane])), __ldg(&bb[128 + lane]));
    float4 b1 = f4add(f4add(__ldg(&bb[lane + 32]), __ldg(&bb[96 + lane])), __ldg(&bb[160 + lane]));
    float4 r0 = f4relu(f4add(a0, b0));
    float4 r1 = f4relu(f4add(a1, b1));

    if (mode == 0) {
        float4* orow = (float4*)(outrow + (size_t)w * 256);
        orow[lane]      = r0;
        orow[lane + 32] = r1;
    } else {
        const float4* wh = (const float4*)Wh;
        float4 q0 = __ldg(&wh[lane]);
        float4 q1 = __ldg(&wh[lane + 32]);
        float s = r0.x * q0.x + r0.y * q0.y + r0.z * q0.z + r0.w * q0.w +
                  r1.x * q1.x + r1.y * q1.y + r1.z * q1.z + r1.w * q1.w;
#pragma unroll
        for (int o = 16; o; o >>= 1) s += __shfl_xor_sync(0xffffffffu, s, o);
        if (lane == 0) headout[w] = 1.f / (1.f + __expf(-(s + bh[0])));
    }
}

// ---------------- host orchestration ----------------
extern "C" void kernel_launch(void* const* d_in, const int* in_sizes, int n_in,
                              void* d_out, int out_size)
{
    const float* z   = (const float*)d_in[0];
    const int*   ei  = (const int*)d_in[1];
    const float* W1  = (const float*)d_in[2];
    const float* as1 = (const float*)d_in[3];
    const float* ad1 = (const float*)d_in[4];
    const float* b1  = (const float*)d_in[5];
    const float* W2  = (const float*)d_in[6];
    const float* as2 = (const float*)d_in[7];
    const float* ad2 = (const float*)d_in[8];
    const float* b2  = (const float*)d_in[9];
    const float* Wh  = (const float*)d_in[10];
    const float* bh  = (const float*)d_in[11];
    float* out = (float*)d_out;

    int n  = in_sizes[0] / 256;   // 50000
    int ne = in_sizes[1] / 6;     // 250000

    void* p;
    cudaGetSymbolAddress(&p, g_hcat); float* hcat = (float*)p;
    cudaGetSymbolAddress(&p, g_h1);   float* h1   = (float*)p;
    cudaGetSymbolAddress(&p, g_as);   float* asb  = (float*)p;
    cudaGetSymbolAddress(&p, g_ad);   float* adb  = (float*)p;
    cudaGetSymbolAddress(&p, g_ws);   float* ws   = (float*)p;
    cudaGetSymbolAddress(&p, g_wd);   float* wd   = (float*)p;
    cudaGetSymbolAddress(&p, g_cnt);  int*   cnt  = (int*)p;
    cudaGetSymbolAddress(&p, g_cur);  int*   cur  = (int*)p;
    cudaGetSymbolAddress(&p, g_off);  int*   off  = (int*)p;
    cudaGetSymbolAddress(&p, g_csr);  int*   csr  = (int*)p;

    cudaFuncSetAttribute(gemm_fused, cudaFuncAttributeMaxDynamicSharedMemorySize, GSMEM);

    // ---- CSR build (graph identical across both layers) ----
    zero_counts<<<(TT * n + 255) / 256, 256>>>(cnt, cur, TT * n);
    hist_kernel<<<(TT * ne + 255) / 256, 256>>>(ei, cnt, n, ne);
    scan_off<<<TT, 1024>>>(cnt, off, n);
    fill_kernel<<<(TT * ne + 255) / 256, 256>>>(ei, off, cur, csr, n, ne);

    dim3 ggrid((n + 127) / 128, 6);

    // ---- layer 1: z -> h1 ----
    wvec_kernel<<<(TT * 256 + 7) / 8, 256>>>(W1, as1, ad1, ws, wd);
    gemm_fused<<<ggrid, 256, GSMEM>>>(z, W1, hcat, n);
    rowdot6<<<(n + 7) / 8, 256>>>(z, ws, wd, asb, adb, n);
    agg_kernel<<<(n + 7) / 8, 256>>>(off, csr, hcat, asb, adb, b1,
                                     h1, Wh, bh, out, 0, n, ne);

    // ---- layer 2: h1 -> head (fused) ----
    wvec_kernel<<<(TT * 256 + 7) / 8, 256>>>(W2, as2, ad2, ws, wd);
    gemm_fused<<<ggrid, 256, GSMEM>>>(h1, W2, hcat, n);
    rowdot6<<<(n + 7) / 8, 256>>>(h1, ws, wd, asb, adb, n);
    agg_kernel<<<(n + 7) / 8, 256>>>(off, csr, hcat, asb, adb, b2,
                                     h1 /*unused*/, Wh, bh, out, 1, n, ne);
}